// round 5
// baseline (speedup 1.0000x reference)
#include <cuda_runtime.h>

// Chamfer distance, pc1/pc2: (1, 16384, 3) fp32 -> scalar fp32.
// fma.rn.f32x2 inner loop; per-query x^2 folded out of the min.
// R4: one resident wave (296 blocks = 148 SM x occ 2), per-block y-slice loop,
//     fused final reduction.

#define P_PTS  16384
#define BLOCK  256
#define RQ     16                   // query points per thread (8 packed pairs)
#define QPB    (BLOCK * RQ)         // 4096 queries per block
#define QTILES (P_PTS / QPB)        // 4
#define NSLICE 37                   // y-slices per (dir,qtile): 8*37 = 296 blocks
#define YS     443                  // ceil(16384/37); last slice = 436

__device__ unsigned int g_min[2][P_PTS];

#define FMA2(out, a, b, c) \
    asm("fma.rn.f32x2 %0, %1, %2, %3;" : "=l"(out) : "l"(a), "l"(b), "l"(c))
#define PACK2(out, lo, hi) \
    asm("mov.b64 %0, {%1, %2};" : "=l"(out) : "f"(lo), "f"(hi))
#define UNPACK2(lo, hi, in) \
    asm("mov.b64 {%0, %1}, %2;" : "=f"(lo), "=f"(hi) : "l"(in))

// Monotone float->uint key: atomicMin on uint == exact float min (deterministic).
__device__ __forceinline__ unsigned int f2key(float f) {
    unsigned int b = __float_as_uint(f);
    unsigned int mask = ((unsigned int)((int)b >> 31)) | 0x80000000u;
    return b ^ mask;
}
__device__ __forceinline__ float key2f(unsigned int k) {
    unsigned int b = (k & 0x80000000u) ? (k ^ 0x80000000u) : ~k;
    return __uint_as_float(b);
}

__global__ void init_kernel() {
    int i = blockIdx.x * blockDim.x + threadIdx.x;
    ((unsigned int*)g_min)[i] = 0xFFFFFFFFu;   // 2*P_PTS entries exactly
}

__global__ void __launch_bounds__(BLOCK, 2) pass_kernel(
    const float* __restrict__ pc1, const float* __restrict__ pc2)
{
    const int combo = blockIdx.y;          // 0..7 : (dir, qtile)
    const int dir   = combo >> 2;
    const int qtile = combo & 3;

    const float* Q;
    const float* Y;
    unsigned int* gm;
    if (dir == 0) { Q = pc1; Y = pc2; gm = g_min[0]; }
    else          { Q = pc2; Y = pc1; gm = g_min[1]; }

    // This block's y-slice, duplicated for packed-broadcast LDS.128:
    // per point: [-2y0,-2y0, -2y1,-2y1, -2y2,-2y2, yy,yy]
    __shared__ float sh[YS * 8];

    const int ybase = blockIdx.x * YS;
    const int ycnt  = min(YS, P_PTS - ybase);   // 443 or 436

    for (int i = threadIdx.x; i < ycnt; i += BLOCK) {
        float y0 = Y[3 * (ybase + i) + 0];
        float y1 = Y[3 * (ybase + i) + 1];
        float y2 = Y[3 * (ybase + i) + 2];
        float yy = y0 * y0 + y1 * y1 + y2 * y2;
        float* s = &sh[i * 8];
        s[0] = -2.0f * y0; s[1] = -2.0f * y0;
        s[2] = -2.0f * y1; s[3] = -2.0f * y1;
        s[4] = -2.0f * y2; s[5] = -2.0f * y2;
        s[6] = yy;         s[7] = yy;
    }
    __syncthreads();

    const int q0 = qtile * QPB + threadIdx.x;

    // 16 query points as 8 packed f32x2 pairs per coordinate.
    unsigned long long Qx[8], Qy[8], Qz[8];
    float m[16];
#pragma unroll
    for (int k = 0; k < 8; k++) {
        int qa = q0 + (2 * k + 0) * BLOCK;
        int qb = q0 + (2 * k + 1) * BLOCK;
        PACK2(Qx[k], Q[3 * qa + 0], Q[3 * qb + 0]);
        PACK2(Qy[k], Q[3 * qa + 1], Q[3 * qb + 1]);
        PACK2(Qz[k], Q[3 * qa + 2], Q[3 * qb + 2]);
        m[2 * k + 0] = __int_as_float(0x7F800000);  // +inf
        m[2 * k + 1] = __int_as_float(0x7F800000);
    }

#pragma unroll 2
    for (int j = 0; j < ycnt; j++) {
        const ulonglong2* sp = (const ulonglong2*)&sh[j * 8];
        ulonglong2 A = sp[0];   // (-2y0,-2y0), (-2y1,-2y1)
        ulonglong2 B = sp[1];   // (-2y2,-2y2), (yy, yy)
#pragma unroll
        for (int k = 0; k < 8; k++) {
            unsigned long long t;
            FMA2(t, Qx[k], A.x, B.y);   // yy - 2*x0*y0
            FMA2(t, Qy[k], A.y, t);
            FMA2(t, Qz[k], B.x, t);     // = yy - 2*(x.y); x^2 added in reduce
            float lo, hi;
            UNPACK2(lo, hi, t);
            m[2 * k + 0] = fminf(m[2 * k + 0], lo);
            m[2 * k + 1] = fminf(m[2 * k + 1], hi);
        }
    }

#pragma unroll
    for (int k = 0; k < RQ; k++) {
        int q = q0 + k * BLOCK;
        atomicMin(&gm[q], f2key(m[k]));
    }
}

// Single-block fused final reduction: add x^2, threshold, sum both directions.
__global__ void __launch_bounds__(1024) reduce_kernel(
    const float* __restrict__ pc1, const float* __restrict__ pc2,
    float* __restrict__ out)
{
    const int tid = threadIdx.x;
    float s = 0.0f;

#pragma unroll
    for (int dir = 0; dir < 2; dir++) {
        const float* X = (dir == 0) ? pc1 : pc2;
        const unsigned int* gm = g_min[dir];
#pragma unroll
        for (int k = 0; k < P_PTS / 1024; k++) {
            int e = tid + k * 1024;
            float v = key2f(gm[e]);
            float x0 = X[3 * e + 0], x1 = X[3 * e + 1], x2 = X[3 * e + 2];
            float d = v + (x0 * x0 + x1 * x1 + x2 * x2);  // full squared NN dist
            if (d < 2.0f) s += d;                          // threshold: >=2 -> 0
        }
    }

#pragma unroll
    for (int o = 16; o; o >>= 1) s += __shfl_xor_sync(0xFFFFFFFFu, s, o);

    __shared__ float ws[32];
    if ((tid & 31) == 0) ws[tid >> 5] = s;
    __syncthreads();
    if (tid < 32) {
        float t = ws[tid];
#pragma unroll
        for (int o = 16; o; o >>= 1) t += __shfl_xor_sync(0xFFFFFFFFu, t, o);
        if (tid == 0) out[0] = t * (1.0f / (float)P_PTS);
    }
}

extern "C" void kernel_launch(void* const* d_in, const int* in_sizes, int n_in,
                              void* d_out, int out_size)
{
    const float* pc1 = (const float*)d_in[0];
    const float* pc2 = (const float*)d_in[1];
    float* out = (float*)d_out;

    init_kernel<<<(2 * P_PTS) / 1024, 1024>>>();
    pass_kernel<<<dim3(NSLICE, 8), BLOCK>>>(pc1, pc2);
    reduce_kernel<<<1, 1024>>>(pc1, pc2, out);
}

// round 6
// speedup vs baseline: 1.1420x; 1.1420x over previous
#include <cuda_runtime.h>

// Chamfer distance, pc1/pc2: (1, 16384, 3) fp32 -> scalar fp32.
// R6: compute each pairwise d2 ONCE, update both directional mins
//     (row-min in registers, column-min via smem strip + atomicMin).
//     Halves the FMA work vs two directional passes.

#define P_PTS  16384
#define BLOCK  256
#define RQ     16                  // query points per thread (8 packed pairs)
#define QPB    (BLOCK * RQ)        // 4096 queries per block
#define QT     (P_PTS / QPB)       // 4 query tiles
#define YS     64                  // y points per block
#define NSL    (P_PTS / YS)        // 256 y-slices
#define STRIP  32                  // column-min strip length
#define CPAD   (BLOCK + 1)         // colbuf row pitch (bank-conflict-free)

__device__ unsigned int g_min[2][P_PTS];

#define FMA2(out, a, b, c) \
    asm("fma.rn.f32x2 %0, %1, %2, %3;" : "=l"(out) : "l"(a), "l"(b), "l"(c))
#define ADD2(out, a, b) \
    asm("add.rn.f32x2 %0, %1, %2;" : "=l"(out) : "l"(a), "l"(b))
#define PACK2(out, lo, hi) \
    asm("mov.b64 %0, {%1, %2};" : "=l"(out) : "f"(lo), "f"(hi))
#define UNPACK2(lo, hi, in) \
    asm("mov.b64 {%0, %1}, %2;" : "=f"(lo), "=f"(hi) : "l"(in))

// Monotone float->uint key: atomicMin on uint == exact float min (deterministic).
__device__ __forceinline__ unsigned int f2key(float f) {
    unsigned int b = __float_as_uint(f);
    unsigned int mask = ((unsigned int)((int)b >> 31)) | 0x80000000u;
    return b ^ mask;
}
__device__ __forceinline__ float key2f(unsigned int k) {
    unsigned int b = (k & 0x80000000u) ? (k ^ 0x80000000u) : ~k;
    return __uint_as_float(b);
}

__global__ void init_kernel() {
    int i = blockIdx.x * blockDim.x + threadIdx.x;
    ((unsigned int*)g_min)[i] = 0xFFFFFFFFu;   // 2*P_PTS entries exactly
}

__global__ void dummy_kernel() {}   // ncu sample-slot alignment only

__global__ void __launch_bounds__(BLOCK, 2) pass_kernel(
    const float* __restrict__ pc1, const float* __restrict__ pc2)
{
    // y tile, duplicated for packed-broadcast LDS.128:
    // per point: [-2y0,-2y0, -2y1,-2y1, -2y2,-2y2, yy,yy]
    __shared__ float shy[YS * 8];
    __shared__ float colbuf[STRIP * CPAD];

    const int tid   = threadIdx.x;
    const int ybase = blockIdx.x * YS;
    const int qtile = blockIdx.y;

    if (tid < YS) {
        int i = tid;
        float y0 = pc2[3 * (ybase + i) + 0];
        float y1 = pc2[3 * (ybase + i) + 1];
        float y2 = pc2[3 * (ybase + i) + 2];
        float yy = y0 * y0 + y1 * y1 + y2 * y2;
        float* s = &shy[i * 8];
        s[0] = -2.0f * y0; s[1] = -2.0f * y0;
        s[2] = -2.0f * y1; s[3] = -2.0f * y1;
        s[4] = -2.0f * y2; s[5] = -2.0f * y2;
        s[6] = yy;         s[7] = yy;
    }

    const int q0 = qtile * QPB + tid;

    // 16 query points as 8 packed pairs; Qw = (xx,xx) per pair.
    unsigned long long Qx[8], Qy[8], Qz[8], Qw[8];
    float m[16];
#pragma unroll
    for (int k = 0; k < 8; k++) {
        int qa = q0 + (2 * k + 0) * BLOCK;
        int qb = q0 + (2 * k + 1) * BLOCK;
        float a0 = pc1[3 * qa + 0], a1 = pc1[3 * qa + 1], a2 = pc1[3 * qa + 2];
        float b0 = pc1[3 * qb + 0], b1 = pc1[3 * qb + 1], b2 = pc1[3 * qb + 2];
        PACK2(Qx[k], a0, b0);
        PACK2(Qy[k], a1, b1);
        PACK2(Qz[k], a2, b2);
        PACK2(Qw[k], a0 * a0 + a1 * a1 + a2 * a2,
                     b0 * b0 + b1 * b1 + b2 * b2);
        m[2 * k + 0] = __int_as_float(0x7F800000);
        m[2 * k + 1] = __int_as_float(0x7F800000);
    }
    __syncthreads();

#pragma unroll 1
    for (int sbase = 0; sbase < YS; sbase += STRIP) {
#pragma unroll 2
        for (int jj = 0; jj < STRIP; jj++) {
            const int j = sbase + jj;
            const ulonglong2* sp = (const ulonglong2*)&shy[j * 8];
            ulonglong2 A = sp[0];   // (-2y0,-2y0), (-2y1,-2y1)
            ulonglong2 B = sp[1];   // (-2y2,-2y2), (yy, yy)
            float ck[8];
#pragma unroll
            for (int k = 0; k < 8; k++) {
                unsigned long long t;
                FMA2(t, Qx[k], A.x, B.y);    // yy - 2 x0 y0
                FMA2(t, Qy[k], A.y, t);
                FMA2(t, Qz[k], B.x, t);
                ADD2(t, t, Qw[k]);           // + xx  -> full d2, packed pair
                float lo, hi;
                UNPACK2(lo, hi, t);
                m[2 * k + 0] = fminf(m[2 * k + 0], lo);
                m[2 * k + 1] = fminf(m[2 * k + 1], hi);
                ck[k] = fminf(lo, hi);
            }
            // column min over this thread's 16 queries (tree)
            float c01 = fminf(ck[0], ck[1]), c23 = fminf(ck[2], ck[3]);
            float c45 = fminf(ck[4], ck[5]), c67 = fminf(ck[6], ck[7]);
            float c = fminf(fminf(c01, c23), fminf(c45, c67));
            colbuf[jj * CPAD + tid] = c;
        }
        __syncthreads();
        // cooperative reduce: 8 threads per j-slot (32 slots)
        {
            int slot  = tid >> 3;
            int lane8 = tid & 7;
            float c = __int_as_float(0x7F800000);
#pragma unroll
            for (int r = 0; r < BLOCK / 8; r++)
                c = fminf(c, colbuf[slot * CPAD + lane8 + 8 * r]);
            c = fminf(c, __shfl_xor_sync(0xFFFFFFFFu, c, 4));
            c = fminf(c, __shfl_xor_sync(0xFFFFFFFFu, c, 2));
            c = fminf(c, __shfl_xor_sync(0xFFFFFFFFu, c, 1));
            if (lane8 == 0)
                atomicMin(&g_min[1][ybase + sbase + slot], f2key(c));
        }
        __syncthreads();
    }

#pragma unroll
    for (int k = 0; k < RQ; k++)
        atomicMin(&g_min[0][q0 + k * BLOCK], f2key(m[k]));
}

// Final reduction: keys already hold full squared NN distances.
__global__ void __launch_bounds__(1024) reduce_kernel(float* __restrict__ out)
{
    const int tid = threadIdx.x;
    float s = 0.0f;
    const unsigned int* gm = (const unsigned int*)g_min;
#pragma unroll
    for (int k = 0; k < (2 * P_PTS) / 1024; k++) {
        float d = key2f(gm[tid + k * 1024]);
        if (d < 2.0f) s += d;                 // threshold: >=2 -> 0
    }
#pragma unroll
    for (int o = 16; o; o >>= 1) s += __shfl_xor_sync(0xFFFFFFFFu, s, o);

    __shared__ float ws[32];
    if ((tid & 31) == 0) ws[tid >> 5] = s;
    __syncthreads();
    if (tid < 32) {
        float t = ws[tid];
#pragma unroll
        for (int o = 16; o; o >>= 1) t += __shfl_xor_sync(0xFFFFFFFFu, t, o);
        if (tid == 0) out[0] = t * (1.0f / (float)P_PTS);
    }
}

extern "C" void kernel_launch(void* const* d_in, const int* in_sizes, int n_in,
                              void* d_out, int out_size)
{
    const float* pc1 = (const float*)d_in[0];
    const float* pc2 = (const float*)d_in[1];
    float* out = (float*)d_out;

    init_kernel<<<(2 * P_PTS) / 1024, 1024>>>();
    dummy_kernel<<<1, 32>>>();                    // slot alignment: pass -> ncu -s 5
    dummy_kernel<<<1, 32>>>();
    pass_kernel<<<dim3(NSL, QT), BLOCK>>>(pc1, pc2);
    reduce_kernel<<<1, 1024>>>(out);
}